// round 16
// baseline (speedup 1.0000x reference)
#include <cuda_runtime.h>
#include <cstdint>

#define H      512
#define NC     64
#define NS     5
#define NQ     15
#define NROWS  1280

__device__ float g_att[NROWS * H];

__device__ __forceinline__ float tanh_approx(float x) {
    float y;
    asm("tanh.approx.f32 %0, %1;" : "=f"(y) : "f"(x));
    return y;
}

__device__ __forceinline__ float to_tf32(float x) {
    uint32_t r;
    asm("cvt.rna.tf32.f32 %0, %1;" : "=r"(r) : "f"(x));
    return __uint_as_float(r);
}

__device__ __forceinline__ void mma_tf32(float& c0, float& c1, float& c2, float& c3,
                                         float a0, float a1, float a2, float a3,
                                         float b0, float b1) {
    asm volatile(
        "mma.sync.aligned.m16n8k8.row.col.f32.tf32.tf32.f32 "
        "{%0,%1,%2,%3}, {%4,%5,%6,%7}, {%8,%9}, {%0,%1,%2,%3};"
        : "+f"(c0), "+f"(c1), "+f"(c2), "+f"(c3)
        : "r"(__float_as_uint(a0)), "r"(__float_as_uint(a1)),
          "r"(__float_as_uint(a2)), "r"(__float_as_uint(a3)),
          "r"(__float_as_uint(b0)), "r"(__float_as_uint(b1)));
}

// ---------------------------------------------------------------------------
// Kernel 1: g_att = X @ W^T + b via tf32 mma.sync.
// Block tile 128(m) x 64(n), 256 threads = 8 warps, warp = 16m x 64n
// (1 m-frag x 8 n-frags). Grid (8 n, 10 m) = 80 blocks -> ONE wave on 148
// SMs (the 160-block version ran a 2nd wave on 12 SMs). BK=32, pitch-36
// SMEM (conflict-free fragment LDS), register prefetch of the next K-slab.
// ---------------------------------------------------------------------------
__global__ __launch_bounds__(256) void gemm_xwt(const float* __restrict__ X,
                                                const float* __restrict__ W,
                                                const float* __restrict__ bias) {
    __shared__ float As[128 * 36];  // [m][k], pitch 36
    __shared__ float Bs[64 * 36];   // [n][k], pitch 36
    __shared__ float sb[64];

    const int t     = threadIdx.x;
    const int warp  = t >> 5;
    const int lane  = t & 31;
    const int m0    = blockIdx.y * 128;
    const int n0    = blockIdx.x * 64;
    const int wm    = warp * 16;                 // warp m offset within tile
    const int group = lane >> 2;                 // 0..7
    const int tid4  = lane & 3;                  // 0..3

    if (t < 64) sb[t] = bias[n0 + t];

    // A: 128 rows x 32 k -> 2 threads/row, 4 float4 each
    const int ar_ = t >> 1;            // 0..127
    const int ak_ = (t & 1) << 4;      // 0 or 16
    // B: 64 rows x 32 k -> 4 threads/row, 2 float4 each
    const int br_ = t >> 2;            // 0..63
    const int bk_ = (t & 3) << 3;      // 0,8,16,24

    float4 a0r, a1r, a2r, a3r, b0r, b1r;

    a0r = *(const float4*)&X[(m0 + ar_) * H + ak_];
    a1r = *(const float4*)&X[(m0 + ar_) * H + ak_ + 4];
    a2r = *(const float4*)&X[(m0 + ar_) * H + ak_ + 8];
    a3r = *(const float4*)&X[(m0 + ar_) * H + ak_ + 12];
    b0r = *(const float4*)&W[(n0 + br_) * H + bk_];
    b1r = *(const float4*)&W[(n0 + br_) * H + bk_ + 4];

    float acc[8][4] = {};   // 8 n-frags x {c0..c3}

    for (int kk = 0; kk < H; kk += 32) {
        {
            float* pa = &As[ar_ * 36 + ak_];
            pa[0]  = to_tf32(a0r.x); pa[1]  = to_tf32(a0r.y);
            pa[2]  = to_tf32(a0r.z); pa[3]  = to_tf32(a0r.w);
            pa[4]  = to_tf32(a1r.x); pa[5]  = to_tf32(a1r.y);
            pa[6]  = to_tf32(a1r.z); pa[7]  = to_tf32(a1r.w);
            pa[8]  = to_tf32(a2r.x); pa[9]  = to_tf32(a2r.y);
            pa[10] = to_tf32(a2r.z); pa[11] = to_tf32(a2r.w);
            pa[12] = to_tf32(a3r.x); pa[13] = to_tf32(a3r.y);
            pa[14] = to_tf32(a3r.z); pa[15] = to_tf32(a3r.w);
            float* pb = &Bs[br_ * 36 + bk_];
            pb[0] = to_tf32(b0r.x); pb[1] = to_tf32(b0r.y);
            pb[2] = to_tf32(b0r.z); pb[3] = to_tf32(b0r.w);
            pb[4] = to_tf32(b1r.x); pb[5] = to_tf32(b1r.y);
            pb[6] = to_tf32(b1r.z); pb[7] = to_tf32(b1r.w);
        }
        __syncthreads();

        if (kk + 32 < H) {
            const int kn = kk + 32;
            a0r = *(const float4*)&X[(m0 + ar_) * H + kn + ak_];
            a1r = *(const float4*)&X[(m0 + ar_) * H + kn + ak_ + 4];
            a2r = *(const float4*)&X[(m0 + ar_) * H + kn + ak_ + 8];
            a3r = *(const float4*)&X[(m0 + ar_) * H + kn + ak_ + 12];
            b0r = *(const float4*)&W[(n0 + br_) * H + kn + bk_];
            b1r = *(const float4*)&W[(n0 + br_) * H + kn + bk_ + 4];
        }

        #pragma unroll
        for (int ks = 0; ks < 32; ks += 8) {
            const float* ar0 = &As[(wm + group) * 36 + ks + tid4];
            const float* ar1 = &As[(wm + group + 8) * 36 + ks + tid4];
            const float fa0 = ar0[0];
            const float fa1 = ar1[0];
            const float fa2 = ar0[4];
            const float fa3 = ar1[4];
            #pragma unroll
            for (int f = 0; f < 8; f++) {
                const float* br = &Bs[(f * 8 + group) * 36 + ks + tid4];
                const float fb0 = br[0];
                const float fb1 = br[4];
                mma_tf32(acc[f][0], acc[f][1], acc[f][2], acc[f][3],
                         fa0, fa1, fa2, fa3, fb0, fb1);
            }
        }
        __syncthreads();
    }

    #pragma unroll
    for (int f = 0; f < 8; f++) {
        const int col = f * 8 + 2 * tid4;
        const float bz0 = sb[col], bz1 = sb[col + 1];
        const int gr0 = m0 + wm + group;
        float2* p0 = (float2*)&g_att[gr0 * H + n0 + col];
        float2* p1 = (float2*)&g_att[(gr0 + 8) * H + n0 + col];
        *p0 = make_float2(acc[f][0] + bz0, acc[f][1] + bz1);
        *p1 = make_float2(acc[f][2] + bz0, acc[f][3] + bz1);
    }
}

// ---------------------------------------------------------------------------
// Kernel 2 (FROZEN = R12, 62.2us = MUFU.TANH floor): 128-thread blocks,
// grid (64, 16), plain MUFU tanh.
// ---------------------------------------------------------------------------
__global__ __launch_bounds__(128, 4) void proto_attn(const float* __restrict__ X,
                                                     float* __restrict__ out) {
    const int c    = blockIdx.x;
    const int qb   = blockIdx.y;
    const int t    = threadIdx.x;
    const int warp = t >> 5;
    const int lane = t & 31;

    __shared__ float4 sA[NS * 128];
    __shared__ float4 sS[NS * 128];

    const float4* attv = (const float4*)g_att;
    const float4* xv   = (const float4*)X;

    for (int i = t; i < NS * 128; i += 128) {
        const int s   = i >> 7;
        const int off = i & 127;
        const int row = c * 20 + s;
        sA[i] = attv[row * 128 + off];
        sS[i] = xv[row * 128 + off];
    }
    __syncthreads();

    const int qc = qb * 4 + warp;

    for (int j = 0; j < NQ; j++) {
        const int row = qc * 20 + NS + j;
        const float4* qa = attv + row * 128;

        float acc[NS] = {0.f, 0.f, 0.f, 0.f, 0.f};
        #pragma unroll
        for (int i = 0; i < 4; i++) {
            const float4 a = qa[lane + i * 32];
            #pragma unroll
            for (int s = 0; s < NS; s++) {
                const float4 b = sA[s * 128 + lane + i * 32];
                acc[s] += tanh_approx(a.x * b.x);
                acc[s] += tanh_approx(a.y * b.y);
                acc[s] += tanh_approx(a.z * b.z);
                acc[s] += tanh_approx(a.w * b.w);
            }
        }
        #pragma unroll
        for (int s = 0; s < NS; s++) {
            #pragma unroll
            for (int o = 16; o > 0; o >>= 1)
                acc[s] += __shfl_xor_sync(0xffffffffu, acc[s], o);
        }

        float m = acc[0];
        #pragma unroll
        for (int s = 1; s < NS; s++) m = fmaxf(m, acc[s]);
        float w[NS];
        float sum = 0.f;
        #pragma unroll
        for (int s = 0; s < NS; s++) { w[s] = __expf(acc[s] - m); sum += w[s]; }
        const float inv = __fdividef(1.0f, sum);
        #pragma unroll
        for (int s = 0; s < NS; s++) w[s] *= inv;

        const float4* qx = xv + row * 128;
        float d = 0.f;
        #pragma unroll
        for (int i = 0; i < 4; i++) {
            const float4 qv = qx[lane + i * 32];
            float px = 0.f, py = 0.f, pz = 0.f, pw = 0.f;
            #pragma unroll
            for (int s = 0; s < NS; s++) {
                const float4 sv = sS[s * 128 + lane + i * 32];
                px = fmaf(w[s], sv.x, px);
                py = fmaf(w[s], sv.y, py);
                pz = fmaf(w[s], sv.z, pz);
                pw = fmaf(w[s], sv.w, pw);
            }
            const float dx = px - qv.x, dy = py - qv.y;
            const float dz = pz - qv.z, dw = pw - qv.w;
            d += dx * dx + dy * dy + dz * dz + dw * dw;
        }
        #pragma unroll
        for (int o = 16; o > 0; o >>= 1)
            d += __shfl_xor_sync(0xffffffffu, d, o);

        if (lane == 0) {
            const int q = qc * NQ + j;
            out[q * NC + c] = d;
        }
    }
}

extern "C" void kernel_launch(void* const* d_in, const int* in_sizes, int n_in,
                              void* d_out, int out_size) {
    const float* x = (const float*)d_in[0];
    const float* W = (const float*)d_in[1];
    const float* b = (const float*)d_in[2];
    float* out = (float*)d_out;

    gemm_xwt<<<dim3(8, 10), 256>>>(x, W, b);
    proto_attn<<<dim3(NC, 16), 128>>>(x, out);
}

// round 17
// speedup vs baseline: 1.0573x; 1.0573x over previous
#include <cuda_runtime.h>
#include <cstdint>

#define H      512
#define NC     64
#define NS     5
#define NQ     15
#define NROWS  1280

__device__ float g_att[NROWS * H];

__device__ __forceinline__ float tanh_approx(float x) {
    float y;
    asm("tanh.approx.f32 %0, %1;" : "=f"(y) : "f"(x));
    return y;
}

__device__ __forceinline__ float to_tf32(float x) {
    uint32_t r;
    asm("cvt.rna.tf32.f32 %0, %1;" : "=r"(r) : "f"(x));
    return __uint_as_float(r);
}

__device__ __forceinline__ void mma_tf32(float& c0, float& c1, float& c2, float& c3,
                                         float a0, float a1, float a2, float a3,
                                         float b0, float b1) {
    asm volatile(
        "mma.sync.aligned.m16n8k8.row.col.f32.tf32.tf32.f32 "
        "{%0,%1,%2,%3}, {%4,%5,%6,%7}, {%8,%9}, {%0,%1,%2,%3};"
        : "+f"(c0), "+f"(c1), "+f"(c2), "+f"(c3)
        : "r"(__float_as_uint(a0)), "r"(__float_as_uint(a1)),
          "r"(__float_as_uint(a2)), "r"(__float_as_uint(a3)),
          "r"(__float_as_uint(b0)), "r"(__float_as_uint(b1)));
}

// ---------------------------------------------------------------------------
// Kernel 1 (R15 shape — measured best: GEMM+gap 11.5us): tf32 mma.sync,
// 64x64 tile, 256 threads, warp 16m x 32n, BK=32, grid (8, 20) = 160 blocks.
// Fires the PDL trigger entering the epilogue so proto_attn can start its
// independent prologue under the GEMM tail.
// ---------------------------------------------------------------------------
__global__ __launch_bounds__(256) void gemm_xwt(const float* __restrict__ X,
                                                const float* __restrict__ W,
                                                const float* __restrict__ bias) {
    __shared__ float As[64 * 36];   // [m][k], pitch 36
    __shared__ float Bs[64 * 36];   // [n][k], pitch 36
    __shared__ float sb[64];

    const int t     = threadIdx.x;
    const int warp  = t >> 5;
    const int lane  = t & 31;
    const int m0    = blockIdx.y * 64;
    const int n0    = blockIdx.x * 64;
    const int wm    = (warp >> 1) * 16;
    const int wn    = (warp & 1) * 32;
    const int group = lane >> 2;
    const int tid4  = lane & 3;

    if (t < 64) sb[t] = bias[n0 + t];

    const int r0  = t >> 3;
    const int c0_ = (t & 7) << 2;

    float4 a0r, a1r, b0r, b1r;
    a0r = *(const float4*)&X[(m0 + r0) * H + c0_];
    a1r = *(const float4*)&X[(m0 + r0 + 32) * H + c0_];
    b0r = *(const float4*)&W[(n0 + r0) * H + c0_];
    b1r = *(const float4*)&W[(n0 + r0 + 32) * H + c0_];

    float acc[4][4] = {};

    for (int kk = 0; kk < H; kk += 32) {
        {
            float* pa0 = &As[r0 * 36 + c0_];
            float* pa1 = &As[(r0 + 32) * 36 + c0_];
            float* pb0 = &Bs[r0 * 36 + c0_];
            float* pb1 = &Bs[(r0 + 32) * 36 + c0_];
            pa0[0] = to_tf32(a0r.x); pa0[1] = to_tf32(a0r.y);
            pa0[2] = to_tf32(a0r.z); pa0[3] = to_tf32(a0r.w);
            pa1[0] = to_tf32(a1r.x); pa1[1] = to_tf32(a1r.y);
            pa1[2] = to_tf32(a1r.z); pa1[3] = to_tf32(a1r.w);
            pb0[0] = to_tf32(b0r.x); pb0[1] = to_tf32(b0r.y);
            pb0[2] = to_tf32(b0r.z); pb0[3] = to_tf32(b0r.w);
            pb1[0] = to_tf32(b1r.x); pb1[1] = to_tf32(b1r.y);
            pb1[2] = to_tf32(b1r.z); pb1[3] = to_tf32(b1r.w);
        }
        __syncthreads();

        if (kk + 32 < H) {
            const int kn = kk + 32;
            a0r = *(const float4*)&X[(m0 + r0) * H + kn + c0_];
            a1r = *(const float4*)&X[(m0 + r0 + 32) * H + kn + c0_];
            b0r = *(const float4*)&W[(n0 + r0) * H + kn + c0_];
            b1r = *(const float4*)&W[(n0 + r0 + 32) * H + kn + c0_];
        }

        #pragma unroll
        for (int ks = 0; ks < 32; ks += 8) {
            const float* ar0 = &As[(wm + group) * 36 + ks + tid4];
            const float* ar1 = &As[(wm + group + 8) * 36 + ks + tid4];
            const float fa0 = ar0[0];
            const float fa1 = ar1[0];
            const float fa2 = ar0[4];
            const float fa3 = ar1[4];
            #pragma unroll
            for (int f = 0; f < 4; f++) {
                const float* br = &Bs[(wn + f * 8 + group) * 36 + ks + tid4];
                mma_tf32(acc[f][0], acc[f][1], acc[f][2], acc[f][3],
                         fa0, fa1, fa2, fa3, br[0], br[4]);
            }
        }
        __syncthreads();
    }

    // PDL: allow proto_attn to launch and run its X-only prologue now.
    cudaTriggerProgrammaticLaunchCompletion();

    #pragma unroll
    for (int f = 0; f < 4; f++) {
        const int col = wn + f * 8 + 2 * tid4;
        const float bz0 = sb[col], bz1 = sb[col + 1];
        const int gr0 = m0 + wm + group;
        float2* p0 = (float2*)&g_att[gr0 * H + n0 + col];
        float2* p1 = (float2*)&g_att[(gr0 + 8) * H + n0 + col];
        *p0 = make_float2(acc[f][0] + bz0, acc[f][1] + bz1);
        *p1 = make_float2(acc[f][2] + bz0, acc[f][3] + bz1);
    }
}

// ---------------------------------------------------------------------------
// Kernel 2 (FROZEN math = R12, MUFU.TANH floor). PDL consumer: loads the
// X-derived support tile first, then cudaGridDependencySynchronize() before
// touching g_att (produced by gemm_xwt).
// ---------------------------------------------------------------------------
__global__ __launch_bounds__(128, 4) void proto_attn(const float* __restrict__ X,
                                                     float* __restrict__ out) {
    const int c    = blockIdx.x;
    const int qb   = blockIdx.y;
    const int t    = threadIdx.x;
    const int warp = t >> 5;
    const int lane = t & 31;

    __shared__ float4 sA[NS * 128];
    __shared__ float4 sS[NS * 128];

    const float4* attv = (const float4*)g_att;
    const float4* xv   = (const float4*)X;

    // Independent prologue: support rows from X (overlaps GEMM tail via PDL)
    for (int i = t; i < NS * 128; i += 128) {
        const int s   = i >> 7;
        const int off = i & 127;
        sS[i] = xv[(c * 20 + s) * 128 + off];
    }

    // Wait for gemm_xwt's g_att to be globally visible
    cudaGridDependencySynchronize();

    for (int i = t; i < NS * 128; i += 128) {
        const int s   = i >> 7;
        const int off = i & 127;
        sA[i] = attv[(c * 20 + s) * 128 + off];
    }
    __syncthreads();

    const int qc = qb * 4 + warp;

    for (int j = 0; j < NQ; j++) {
        const int row = qc * 20 + NS + j;
        const float4* qa = attv + row * 128;

        float acc[NS] = {0.f, 0.f, 0.f, 0.f, 0.f};
        #pragma unroll
        for (int i = 0; i < 4; i++) {
            const float4 a = qa[lane + i * 32];
            #pragma unroll
            for (int s = 0; s < NS; s++) {
                const float4 b = sA[s * 128 + lane + i * 32];
                acc[s] += tanh_approx(a.x * b.x);
                acc[s] += tanh_approx(a.y * b.y);
                acc[s] += tanh_approx(a.z * b.z);
                acc[s] += tanh_approx(a.w * b.w);
            }
        }
        #pragma unroll
        for (int s = 0; s < NS; s++) {
            #pragma unroll
            for (int o = 16; o > 0; o >>= 1)
                acc[s] += __shfl_xor_sync(0xffffffffu, acc[s], o);
        }

        float m = acc[0];
        #pragma unroll
        for (int s = 1; s < NS; s++) m = fmaxf(m, acc[s]);
        float w[NS];
        float sum = 0.f;
        #pragma unroll
        for (int s = 0; s < NS; s++) { w[s] = __expf(acc[s] - m); sum += w[s]; }
        const float inv = __fdividef(1.0f, sum);
        #pragma unroll
        for (int s = 0; s < NS; s++) w[s] *= inv;

        const float4* qx = xv + row * 128;
        float d = 0.f;
        #pragma unroll
        for (int i = 0; i < 4; i++) {
            const float4 qv = qx[lane + i * 32];
            float px = 0.f, py = 0.f, pz = 0.f, pw = 0.f;
            #pragma unroll
            for (int s = 0; s < NS; s++) {
                const float4 sv = sS[s * 128 + lane + i * 32];
                px = fmaf(w[s], sv.x, px);
                py = fmaf(w[s], sv.y, py);
                pz = fmaf(w[s], sv.z, pz);
                pw = fmaf(w[s], sv.w, pw);
            }
            const float dx = px - qv.x, dy = py - qv.y;
            const float dz = pz - qv.z, dw = pw - qv.w;
            d += dx * dx + dy * dy + dz * dz + dw * dw;
        }
        #pragma unroll
        for (int o = 16; o > 0; o >>= 1)
            d += __shfl_xor_sync(0xffffffffu, d, o);

        if (lane == 0) {
            const int q = qc * NQ + j;
            out[q * NC + c] = d;
        }
    }
}

extern "C" void kernel_launch(void* const* d_in, const int* in_sizes, int n_in,
                              void* d_out, int out_size) {
    const float* x = (const float*)d_in[0];
    const float* W = (const float*)d_in[1];
    const float* b = (const float*)d_in[2];
    float* out = (float*)d_out;

    gemm_xwt<<<dim3(8, 20), 256>>>(x, W, b);

    // proto_attn with Programmatic Dependent Launch: may begin while gemm_xwt
    // drains; correctness enforced by cudaGridDependencySynchronize() inside.
    cudaLaunchConfig_t cfg = {};
    cfg.gridDim  = dim3(NC, 16);
    cfg.blockDim = dim3(128);
    cfg.dynamicSmemBytes = 0;
    cfg.stream = 0;
    cudaLaunchAttribute attrs[1];
    attrs[0].id = cudaLaunchAttributeProgrammaticStreamSerialization;
    attrs[0].val.programmaticStreamSerializationAllowed = 1;
    cfg.attrs = attrs;
    cfg.numAttrs = 1;
    cudaLaunchKernelEx(&cfg, proto_attn, x, out);
}